// round 10
// baseline (speedup 1.0000x reference)
#include <cuda_runtime.h>

typedef unsigned int u32;

#define IN_PN  20000
#define OUT_PN 5000
#define MNB    9
#define CIN    32
#define COUT   64
#define SLOT   36                 /* padded row stride (floats) */
#define TILEF  (64 * SLOT)        /* floats per 64x32 tile */
#define TB     (TILEF * 4)        /* tile bytes = 9216 */
/* layout: A0,A1,A2 @ 0,1,2*TILEF ; W0,W1,W2 @ 3,4,5*TILEF ; header @ 6*TILEF */
#define SMEM_FLOATS (6 * TILEF + 32)

__device__ __forceinline__ u32 tf32c(float x) {
    u32 r; asm("cvt.rna.tf32.f32 %0, %1;" : "=r"(r) : "f"(x)); return r;
}
__device__ __forceinline__ void mma8(float d[4], u32 a0, u32 a1, u32 a2, u32 a3,
                                     u32 b0, u32 b1) {
    asm("mma.sync.aligned.m16n8k8.row.col.f32.tf32.tf32.f32 "
        "{%0,%1,%2,%3}, {%4,%5,%6,%7}, {%8,%9}, {%0,%1,%2,%3};"
        : "+f"(d[0]), "+f"(d[1]), "+f"(d[2]), "+f"(d[3])
        : "r"(a0), "r"(a1), "r"(a2), "r"(a3), "r"(b0), "r"(b1));
}
__device__ __forceinline__ void ldsm4(u32 r[4], u32 addr) {
    asm volatile("ldmatrix.sync.aligned.m8n8.x4.shared.b16 {%0,%1,%2,%3}, [%4];"
                 : "=r"(r[0]), "=r"(r[1]), "=r"(r[2]), "=r"(r[3]) : "r"(addr));
}
__device__ __forceinline__ void cpasync16(u32 dst, const float* src) {
    asm volatile("cp.async.cg.shared.global [%0], [%1], 16;" :: "r"(dst), "l"(src));
}
__device__ __forceinline__ void cpasync16z(u32 dst, const float* src, u32 src_bytes) {
    asm volatile("cp.async.cg.shared.global [%0], [%1], 16, %2;"
                 :: "r"(dst), "l"(src), "r"(src_bytes));
}
__device__ __forceinline__ void cpcommit() {
    asm volatile("cp.async.commit_group;" ::: "memory");
}
__device__ __forceinline__ void cpwait0() {
    asm volatile("cp.async.wait_group 0;" ::: "memory");
}
__device__ __forceinline__ void cpwait1() {
    asm volatile("cp.async.wait_group 1;" ::: "memory");
}

// one 64x64x32 slice for this warp's 32b x 32o tile.
// A tile: raw fp32 (MMA truncates to tf32; bias corrected in epilogue).
// W tile: raw fp32, rna-cvt at read (idempotent if already tf32).
__device__ __forceinline__ void slice_mma(u32 aA0, u32 aA1, u32 wA,
                                          float acc[2][4][4])
{
    #pragma unroll
    for (int kk = 0; kk < 4; kk++) {
        u32 a0[4], a1[4], w0[4], w1[4];
        ldsm4(a0, aA0); ldsm4(a1, aA1);
        ldsm4(w0, wA);  ldsm4(w1, wA + 16);
        aA0 += 32; aA1 += 32; wA += 32;
        #pragma unroll
        for (int j = 0; j < 4; j++) {
            u32 b0 = tf32c(__uint_as_float(w0[j]));
            u32 b1 = tf32c(__uint_as_float(w1[j]));
            mma8(acc[0][j], a0[0], a0[1], a0[2], a0[3], b0, b1);
            mma8(acc[1][j], a1[0], a1[1], a1[2], a1[3], b0, b1);
        }
    }
}

__device__ __forceinline__ void ldg16(float v[16], const float* __restrict__ src) {
    #pragma unroll
    for (int j = 0; j < 4; j++) {
        float4 a = ((const float4*)src)[j];
        v[4*j+0] = a.x; v[4*j+1] = a.y; v[4*j+2] = a.z; v[4*j+3] = a.w;
    }
}
__device__ __forceinline__ void sts16(float* dst, const float v[16], float sc) {
    #pragma unroll
    for (int j = 0; j < 4; j++) {
        uint4 x;
        x.x = tf32c(v[4*j+0] * sc); x.y = tf32c(v[4*j+1] * sc);
        x.z = tf32c(v[4*j+2] * sc); x.w = tf32c(v[4*j+3] * sc);
        ((uint4*)dst)[j] = x;
    }
}

__global__ __launch_bounds__(128, 4)
void pconv_mma(const float* __restrict__ in_pc,
               const int*   __restrict__ nid_g,
               const float* __restrict__ wts,
               const float* __restrict__ bias,
               const float* __restrict__ pnb,
               const float* __restrict__ wres,
               float* __restrict__ out)
{
    extern __shared__ float sm[];
    float* pm_s  = sm + 6 * TILEF;
    int*   nid_s = (int*)(sm + 6 * TILEF + 16);

    const int tid  = threadIdx.x;
    const int lane = tid & 31;
    const int wid  = tid >> 5;
    const int p    = blockIdx.x;

    const int bg  = (wid >> 1) * 32;
    const int og  = (wid & 1) * 32;
    const int g   = lane >> 2;
    const int tig = lane & 3;

    const int srow = tid >> 1;
    const int scol = (tid & 1) * 16;

    if (tid < MNB) {
        int nv = nid_g[p * MNB + tid];
        nid_s[tid] = nv;
        pm_s[tid] = (nv != IN_PN) ? fabsf(pnb[p * MNB + tid]) : 0.0f;
    }
    __syncthreads();
    if (tid == 0) {
        float s = 1e-8f;
        #pragma unroll
        for (int m = 0; m < MNB; m++) s += pm_s[m];
        float inv = 1.0f / s;
        #pragma unroll
        for (int m = 0; m < MNB; m++) pm_s[m] *= inv;
    }
    __syncthreads();

    const float* wp    = wts + (size_t)p * (MNB * CIN * COUT);
    const float* inrow = in_pc + (size_t)srow * (IN_PN * CIN) + scol;
    const u32 smb = (u32)__cvta_generic_to_shared(sm);

    // ldmatrix lane addresses within A0 / W0 (verified mapping)
    const u32 aFrag = smb + (u32)(bg + (lane & 15)) * (SLOT * 4u) + (u32)(lane >> 4) * 16u;
    const u32 wFrag = smb + (u32)(3 * TB) + (u32)(og + lane) * (SLOT * 4u);
    const u32 aHalf = 16u * SLOT * 4u;
    const u32 stOff = (u32)(srow * SLOT + scol) * 4u;

    // stage slice s into buffer buf (In -> A[buf], W -> W[buf]), one group
    #define STAGE(s, buf)                                                        \
    do {                                                                         \
        const float* wsrc_ = wp + (size_t)(s) * (CIN * COUT)                     \
                           + (size_t)srow * CIN + scol;                          \
        u32 wdst_ = smb + (u32)(3 + (buf)) * TB + stOff;                         \
        _Pragma("unroll")                                                        \
        for (int j = 0; j < 4; j++) cpasync16(wdst_ + 16u * j, wsrc_ + 4 * j);   \
        int nv_ = nid_s[s];                                                      \
        const float* isrc_ = inrow + (size_t)((nv_ == IN_PN) ? 0 : nv_) * CIN;   \
        u32 sb_ = (nv_ == IN_PN) ? 0u : 16u;                                     \
        u32 adst_ = smb + (u32)(buf) * TB + stOff;                               \
        _Pragma("unroll")                                                        \
        for (int j = 0; j < 4; j++) cpasync16z(adst_ + 16u * j, isrc_ + 4 * j, sb_); \
        cpcommit();                                                             \
    } while (0)

    float rs[16];
    #pragma unroll
    for (int i = 0; i < 16; i++) rs[i] = 0.0f;

    // ---- prologue: two slices in flight ----
    STAGE(0, 0);
    STAGE(1, 1);
    cpwait1();          // group 0 landed
    __syncthreads();

    float acc[2][4][4];
    #pragma unroll
    for (int b = 0; b < 2; b++)
        #pragma unroll
        for (int j = 0; j < 4; j++)
            #pragma unroll
            for (int e = 0; e < 4; e++) acc[b][j][e] = 0.0f;

    // ---- main loop: 3-stage pipeline, fully unrolled ----
    #pragma unroll
    for (int m = 0; m < MNB; m++) {
        const u32 cur = (u32)(m % 3) * TB;

        if (m + 2 < MNB) STAGE(m + 2, (m + 2) % 3);

        slice_mma(aFrag + cur, aFrag + cur + aHalf, wFrag + cur, acc);

        // residual pre-reduction from the current (resident) A tile
        {
            const float* at = sm + (cur >> 2) + srow * SLOT + scol;
            const float pmv = pm_s[m];
            #pragma unroll
            for (int j = 0; j < 4; j++) {
                float4 q = ((const float4*)at)[j];
                rs[4*j+0] = fmaf(pmv, q.x, rs[4*j+0]);
                rs[4*j+1] = fmaf(pmv, q.y, rs[4*j+1]);
                rs[4*j+2] = fmaf(pmv, q.z, rs[4*j+2]);
                rs[4*j+3] = fmaf(pmv, q.w, rs[4*j+3]);
            }
        }

        if (m < MNB - 1) {
            if (m + 2 < MNB) cpwait1(); else cpwait0();
            __syncthreads();
        }
    }

    // ---- residual slice into buffers 0 (slice 8 used buffer 2) ----
    const float C = 0.70710678118654752f;   // sqrt(0.5)
    sts16(sm + srow * SLOT + scol, rs, 1.0f);             // A0 <- rs (rna cvt)
    {
        float vw[16];
        ldg16(vw, wres + (size_t)srow * CIN + scol);
        sts16(sm + 3 * TILEF + srow * SLOT + scol, vw, C); // W0 <- sqrt(RR)*wres
    }

    // acc <- C * elu(corr*acc + bias); corr cancels A-side tf32 truncation bias
    const float CORR = 1.000338f;            // 1 + 2^-11 * ln2
    const float* brow = bias + (size_t)p * COUT;
    #pragma unroll
    for (int j = 0; j < 4; j++) {
        const int o0 = og + 8 * j + 2 * tig;
        float2 bb = *(const float2*)(brow + o0);
        #pragma unroll
        for (int b = 0; b < 2; b++) {
            float x0 = fmaf(acc[b][j][0], CORR, bb.x);
            float x1 = fmaf(acc[b][j][1], CORR, bb.y);
            float x2 = fmaf(acc[b][j][2], CORR, bb.x);
            float x3 = fmaf(acc[b][j][3], CORR, bb.y);
            x0 = (x0 > 0.0f) ? x0 : expm1f(x0);
            x1 = (x1 > 0.0f) ? x1 : expm1f(x1);
            x2 = (x2 > 0.0f) ? x2 : expm1f(x2);
            x3 = (x3 > 0.0f) ? x3 : expm1f(x3);
            acc[b][j][0] = C * x0; acc[b][j][1] = C * x1;
            acc[b][j][2] = C * x2; acc[b][j][3] = C * x3;
        }
    }
    __syncthreads();

    // residual MMA accumulates in place (buffer 0; both operands rna tf32)
    slice_mma(aFrag, aFrag + aHalf, wFrag, acc);

    // ---- store: out[b][p][o] ----
    #pragma unroll
    for (int j = 0; j < 4; j++) {
        const int o0 = og + 8 * j + 2 * tig;
        #pragma unroll
        for (int b = 0; b < 2; b++) {
            const int r0 = bg + 16 * b + g;
            float2 v0 = { acc[b][j][0], acc[b][j][1] };
            float2 v1 = { acc[b][j][2], acc[b][j][3] };
            *(float2*)(out + ((size_t)r0       * OUT_PN + p) * COUT + o0) = v0;
            *(float2*)(out + ((size_t)(r0 + 8) * OUT_PN + p) * COUT + o0) = v1;
        }
    }
    #undef STAGE
}

extern "C" void kernel_launch(void* const* d_in, const int* in_sizes, int n_in,
                              void* d_out, int out_size)
{
    const float* in_pc = (const float*)d_in[0];
    const int*   nid   = (const int*)  d_in[1];
    const float* wts   = (const float*)d_in[2];
    const float* bias  = (const float*)d_in[3];
    const float* pnb   = (const float*)d_in[4];
    const float* wres  = (const float*)d_in[5];
    float* out = (float*)d_out;

    const int smem_bytes = SMEM_FLOATS * sizeof(float);   // ~55.4 KB
    cudaFuncSetAttribute(pconv_mma,
                         cudaFuncAttributeMaxDynamicSharedMemorySize, smem_bytes);
    pconv_mma<<<OUT_PN, 128, smem_bytes>>>(in_pc, nid, wts, bias, pnb, wres, out);
}

// round 11
// speedup vs baseline: 1.0353x; 1.0353x over previous
#include <cuda_runtime.h>

typedef unsigned int u32;

#define IN_PN  20000
#define OUT_PN 5000
#define MNB    9
#define CIN    32
#define COUT   64
#define SLOT   36                 /* padded row stride (floats) */
#define TILEF  (64 * SLOT)        /* floats per 64x32 tile */
#define TB     (TILEF * 4)        /* tile bytes = 9216 */
/* A tiles @ 0,1,2*TILEF ; W tiles @ 3,4,5*TILEF ; header @ 6*TILEF */
#define SMEM_FLOATS (6 * TILEF + 32)

__device__ __forceinline__ u32 tf32c(float x) {
    u32 r; asm("cvt.rna.tf32.f32 %0, %1;" : "=r"(r) : "f"(x)); return r;
}
__device__ __forceinline__ void mma8(float d[4], u32 a0, u32 a1, u32 a2, u32 a3,
                                     u32 b0, u32 b1) {
    asm("mma.sync.aligned.m16n8k8.row.col.f32.tf32.tf32.f32 "
        "{%0,%1,%2,%3}, {%4,%5,%6,%7}, {%8,%9}, {%0,%1,%2,%3};"
        : "+f"(d[0]), "+f"(d[1]), "+f"(d[2]), "+f"(d[3])
        : "r"(a0), "r"(a1), "r"(a2), "r"(a3), "r"(b0), "r"(b1));
}
__device__ __forceinline__ void ldsm4(u32 r[4], u32 addr) {
    asm volatile("ldmatrix.sync.aligned.m8n8.x4.shared.b16 {%0,%1,%2,%3}, [%4];"
                 : "=r"(r[0]), "=r"(r[1]), "=r"(r[2]), "=r"(r[3]) : "r"(addr));
}
__device__ __forceinline__ void cpasync16(u32 dst, const float* src) {
    asm volatile("cp.async.cg.shared.global [%0], [%1], 16;" :: "r"(dst), "l"(src));
}
__device__ __forceinline__ void cpasync16z(u32 dst, const float* src, u32 src_bytes) {
    asm volatile("cp.async.cg.shared.global [%0], [%1], 16, %2;"
                 :: "r"(dst), "l"(src), "r"(src_bytes));
}
__device__ __forceinline__ void cpcommit() {
    asm volatile("cp.async.commit_group;" ::: "memory");
}
__device__ __forceinline__ void cpwait0() {
    asm volatile("cp.async.wait_group 0;" ::: "memory");
}
__device__ __forceinline__ void cpwait1() {
    asm volatile("cp.async.wait_group 1;" ::: "memory");
}

// one 64x64x32 slice for this warp's 32b x 32o tile.
// A: raw fp32 (MMA truncates to tf32; bias-corrected in epilogue).
// W: raw fp32, rna-cvt at fragment read (idempotent if already tf32).
__device__ __forceinline__ void slice_mma(u32 aA0, u32 aA1, u32 wA,
                                          float acc[2][4][4])
{
    #pragma unroll
    for (int kk = 0; kk < 4; kk++) {
        u32 a0[4], a1[4], w0[4], w1[4];
        ldsm4(a0, aA0); ldsm4(a1, aA1);
        ldsm4(w0, wA);  ldsm4(w1, wA + 16);
        aA0 += 32; aA1 += 32; wA += 32;
        #pragma unroll
        for (int j = 0; j < 4; j++) {
            u32 b0 = tf32c(__uint_as_float(w0[j]));
            u32 b1 = tf32c(__uint_as_float(w1[j]));
            mma8(acc[0][j], a0[0], a0[1], a0[2], a0[3], b0, b1);
            mma8(acc[1][j], a1[0], a1[1], a1[2], a1[3], b0, b1);
        }
    }
}

__device__ __forceinline__ void ldg16(float v[16], const float* __restrict__ src) {
    #pragma unroll
    for (int j = 0; j < 4; j++) {
        float4 a = ((const float4*)src)[j];
        v[4*j+0] = a.x; v[4*j+1] = a.y; v[4*j+2] = a.z; v[4*j+3] = a.w;
    }
}
__device__ __forceinline__ void sts16(float* dst, const float v[16], float sc) {
    #pragma unroll
    for (int j = 0; j < 4; j++) {
        uint4 x;
        x.x = tf32c(v[4*j+0] * sc); x.y = tf32c(v[4*j+1] * sc);
        x.z = tf32c(v[4*j+2] * sc); x.w = tf32c(v[4*j+3] * sc);
        ((uint4*)dst)[j] = x;
    }
}

// stage slice: W(8KB) + gathered In(8KB) into buffer at byte offset `buf`
__device__ __forceinline__ void stage(const float* __restrict__ wsl,
                                      const float* __restrict__ inrow,
                                      int nv, u32 smb, u32 buf, u32 stOff)
{
    u32 wdst = smb + 3u * TB + buf + stOff;
    #pragma unroll
    for (int j = 0; j < 4; j++) cpasync16(wdst + 16u * j, wsl + 4 * j);

    const float* isrc = inrow + (size_t)((nv == IN_PN) ? 0 : nv) * CIN;
    u32 sb = (nv == IN_PN) ? 0u : 16u;
    u32 adst = smb + buf + stOff;
    #pragma unroll
    for (int j = 0; j < 4; j++) cpasync16z(adst + 16u * j, isrc + 4 * j, sb);
    cpcommit();
}

__global__ __launch_bounds__(128, 4)
void pconv_mma(const float* __restrict__ in_pc,
               const int*   __restrict__ nid_g,
               const float* __restrict__ wts,
               const float* __restrict__ bias,
               const float* __restrict__ pnb,
               const float* __restrict__ wres,
               float* __restrict__ out)
{
    extern __shared__ float sm[];
    float* pm_s  = sm + 6 * TILEF;
    int*   nid_s = (int*)(sm + 6 * TILEF + 16);

    const int tid  = threadIdx.x;
    const int lane = tid & 31;
    const int wid  = tid >> 5;
    const int p    = blockIdx.x;

    const int bg  = (wid >> 1) * 32;
    const int og  = (wid & 1) * 32;
    const int g   = lane >> 2;
    const int tig = lane & 3;

    const int srow = tid >> 1;
    const int scol = (tid & 1) * 16;

    if (tid < MNB) {
        int nv = nid_g[p * MNB + tid];
        nid_s[tid] = nv;
        pm_s[tid] = (nv != IN_PN) ? fabsf(pnb[p * MNB + tid]) : 0.0f;
    }
    __syncthreads();
    if (tid == 0) {
        float s = 1e-8f;
        #pragma unroll
        for (int m = 0; m < MNB; m++) s += pm_s[m];
        float inv = 1.0f / s;
        #pragma unroll
        for (int m = 0; m < MNB; m++) pm_s[m] *= inv;
    }
    __syncthreads();

    const float* wsl   = wts + (size_t)p * (MNB * CIN * COUT)
                       + (size_t)srow * CIN + scol;      // per-thread W src
    const float* inrow = in_pc + (size_t)srow * (IN_PN * CIN) + scol;
    const u32 smb = (u32)__cvta_generic_to_shared(sm);

    // ldmatrix lane addresses within buffer 0 (verified mapping)
    const u32 aFrag = smb + (u32)(bg + (lane & 15)) * (SLOT * 4u) + (u32)(lane >> 4) * 16u;
    const u32 wFrag = smb + (u32)(3 * TB) + (u32)(og + lane) * (SLOT * 4u);
    const u32 aHalf = 16u * SLOT * 4u;
    const u32 stOff = (u32)(srow * SLOT + scol) * 4u;

    float rs[16];
    #pragma unroll
    for (int i = 0; i < 16; i++) rs[i] = 0.0f;

    // ---- prologue: two stage-groups in flight ----
    stage(wsl,                    inrow, nid_s[0], smb, 0u,      stOff);
    stage(wsl + 1 * (CIN * COUT), inrow, nid_s[1], smb, (u32)TB, stOff);
    cpwait1();           // group 0 landed
    __syncthreads();

    float acc[2][4][4];
    #pragma unroll
    for (int b = 0; b < 2; b++)
        #pragma unroll
        for (int j = 0; j < 4; j++)
            #pragma unroll
            for (int e = 0; e < 4; e++) acc[b][j][e] = 0.0f;

    // rotating buffer byte-offsets: cur (compute), nxt (landing), fre (stage m+2)
    u32 cur = 0u, nxt = (u32)TB, fre = 2u * (u32)TB;

    #pragma unroll 1
    for (int m = 0; m < MNB; m++) {
        if (m + 2 < MNB)
            stage(wsl + (size_t)(m + 2) * (CIN * COUT), inrow, nid_s[m + 2],
                  smb, fre, stOff);

        slice_mma(aFrag + cur, aFrag + cur + aHalf, wFrag + cur, acc);

        // residual pre-reduction from the current (resident) A tile
        {
            const float* at = sm + (cur >> 2) + srow * SLOT + scol;
            const float pmv = pm_s[m];
            #pragma unroll
            for (int j = 0; j < 4; j++) {
                float4 q = ((const float4*)at)[j];
                rs[4*j+0] = fmaf(pmv, q.x, rs[4*j+0]);
                rs[4*j+1] = fmaf(pmv, q.y, rs[4*j+1]);
                rs[4*j+2] = fmaf(pmv, q.z, rs[4*j+2]);
                rs[4*j+3] = fmaf(pmv, q.w, rs[4*j+3]);
            }
        }

        if (m < MNB - 1) {
            if (m + 2 < MNB) cpwait1(); else cpwait0();
            __syncthreads();
        }
        u32 t = cur; cur = nxt; nxt = fre; fre = t;
    }

    // ---- residual slice into a freed buffer (nxt is free: last read at m=6) ----
    const float C = 0.70710678118654752f;   // sqrt(0.5)
    sts16(sm + (nxt >> 2) + srow * SLOT + scol, rs, 1.0f);       // A <- rs (rna)
    {
        float vw[16];
        ldg16(vw, wres + (size_t)srow * CIN + scol);
        sts16(sm + (3 * TB + nxt >> 2) + srow * SLOT + scol, vw, C);
    }

    // acc <- C * elu(corr*acc + bias); corr cancels A-side tf32 truncation bias
    const float CORR = 1.000338f;            // 1 + 2^-11 * ln2
    const float* brow = bias + (size_t)p * COUT;
    #pragma unroll
    for (int j = 0; j < 4; j++) {
        const int o0 = og + 8 * j + 2 * tig;
        float2 bb = *(const float2*)(brow + o0);
        #pragma unroll
        for (int b = 0; b < 2; b++) {
            float x0 = fmaf(acc[b][j][0], CORR, bb.x);
            float x1 = fmaf(acc[b][j][1], CORR, bb.y);
            float x2 = fmaf(acc[b][j][2], CORR, bb.x);
            float x3 = fmaf(acc[b][j][3], CORR, bb.y);
            x0 = (x0 > 0.0f) ? x0 : expm1f(x0);
            x1 = (x1 > 0.0f) ? x1 : expm1f(x1);
            x2 = (x2 > 0.0f) ? x2 : expm1f(x2);
            x3 = (x3 > 0.0f) ? x3 : expm1f(x3);
            acc[b][j][0] = C * x0; acc[b][j][1] = C * x1;
            acc[b][j][2] = C * x2; acc[b][j][3] = C * x3;
        }
    }
    __syncthreads();

    // residual MMA accumulates in place (both operands rna tf32 — unbiased)
    slice_mma(aFrag + nxt, aFrag + nxt + aHalf, wFrag + nxt, acc);

    // ---- store: out[b][p][o] ----
    #pragma unroll
    for (int j = 0; j < 4; j++) {
        const int o0 = og + 8 * j + 2 * tig;
        #pragma unroll
        for (int b = 0; b < 2; b++) {
            const int r0 = bg + 16 * b + g;
            float2 v0 = { acc[b][j][0], acc[b][j][1] };
            float2 v1 = { acc[b][j][2], acc[b][j][3] };
            *(float2*)(out + ((size_t)r0       * OUT_PN + p) * COUT + o0) = v0;
            *(float2*)(out + ((size_t)(r0 + 8) * OUT_PN + p) * COUT + o0) = v1;
        }
    }
}

extern "C" void kernel_launch(void* const* d_in, const int* in_sizes, int n_in,
                              void* d_out, int out_size)
{
    const float* in_pc = (const float*)d_in[0];
    const int*   nid   = (const int*)  d_in[1];
    const float* wts   = (const float*)d_in[2];
    const float* bias  = (const float*)d_in[3];
    const float* pnb   = (const float*)d_in[4];
    const float* wres  = (const float*)d_in[5];
    float* out = (float*)d_out;

    const int smem_bytes = SMEM_FLOATS * sizeof(float);   // ~55.4 KB
    cudaFuncSetAttribute(pconv_mma,
                         cudaFuncAttributeMaxDynamicSharedMemorySize, smem_bytes);
    pconv_mma<<<OUT_PN, 128, smem_bytes>>>(in_pc, nid, wts, bias, pnb, wres, out);
}

// round 12
// speedup vs baseline: 1.0855x; 1.0484x over previous
#include <cuda_runtime.h>

typedef unsigned int u32;

#define IN_PN  20000
#define OUT_PN 5000
#define MNB    9
#define CIN    32
#define COUT   64
#define SLOT   36                 /* padded row stride (floats) */
#define TILEF  (64 * SLOT)        /* floats per 64x32 tile */
#define TB     (TILEF * 4)        /* tile bytes = 9216 */

__device__ __forceinline__ u32 tf32c(float x) {
    u32 r; asm("cvt.rna.tf32.f32 %0, %1;" : "=r"(r) : "f"(x)); return r;
}
__device__ __forceinline__ void mma8(float d[4], u32 a0, u32 a1, u32 a2, u32 a3,
                                     u32 b0, u32 b1) {
    asm("mma.sync.aligned.m16n8k8.row.col.f32.tf32.tf32.f32 "
        "{%0,%1,%2,%3}, {%4,%5,%6,%7}, {%8,%9}, {%0,%1,%2,%3};"
        : "+f"(d[0]), "+f"(d[1]), "+f"(d[2]), "+f"(d[3])
        : "r"(a0), "r"(a1), "r"(a2), "r"(a3), "r"(b0), "r"(b1));
}
__device__ __forceinline__ void ldsm4(u32 r[4], u32 addr) {
    asm volatile("ldmatrix.sync.aligned.m8n8.x4.shared.b16 {%0,%1,%2,%3}, [%4];"
                 : "=r"(r[0]), "=r"(r[1]), "=r"(r[2]), "=r"(r[3]) : "r"(addr));
}
__device__ __forceinline__ void cpasync16(u32 dst, const float* src) {
    asm volatile("cp.async.cg.shared.global [%0], [%1], 16;" :: "r"(dst), "l"(src));
}
// zfill variant: copies src_bytes (0 or 16), zero-fills the rest of 16B
__device__ __forceinline__ void cpasync16z(u32 dst, const float* src, u32 src_bytes) {
    asm volatile("cp.async.cg.shared.global [%0], [%1], 16, %2;"
                 :: "r"(dst), "l"(src), "r"(src_bytes));
}
__device__ __forceinline__ void cpcommit() {
    asm volatile("cp.async.commit_group;" ::: "memory");
}
__device__ __forceinline__ void cpwait0() {
    asm volatile("cp.async.wait_group 0;" ::: "memory");
}

// one 64x64x32 slice for this warp's 32b x 32o tile.
// BOTH operands raw fp32: the tf32 MMA ignores the low 13 mantissa bits
// (truncation). The resulting multiplicative bias (1+2^-11*ln2)^2 is
// corrected in the epilogue. Tiles that were staged through rna tf32 cvt
// (residual rs / wres) are unaffected: truncation of tf32 is identity.
__device__ __forceinline__ void slice_mma(u32 aA0, u32 aA1, u32 wA,
                                          float acc[2][4][4])
{
    #pragma unroll
    for (int kk = 0; kk < 4; kk++) {
        u32 a0[4], a1[4], w0[4], w1[4];
        ldsm4(a0, aA0); ldsm4(a1, aA1);
        ldsm4(w0, wA);  ldsm4(w1, wA + 16);
        aA0 += 32; aA1 += 32; wA += 32;
        #pragma unroll
        for (int j = 0; j < 4; j++) {
            mma8(acc[0][j], a0[0], a0[1], a0[2], a0[3], w0[j], w1[j]);
            mma8(acc[1][j], a1[0], a1[1], a1[2], a1[3], w0[j], w1[j]);
        }
    }
}

__device__ __forceinline__ void ldg16(float v[16], const float* __restrict__ src) {
    #pragma unroll
    for (int j = 0; j < 4; j++) {
        float4 a = ((const float4*)src)[j];
        v[4*j+0] = a.x; v[4*j+1] = a.y; v[4*j+2] = a.z; v[4*j+3] = a.w;
    }
}
__device__ __forceinline__ void sts16(float* dst, const float v[16], float sc) {
    #pragma unroll
    for (int j = 0; j < 4; j++) {
        uint4 x;
        x.x = tf32c(v[4*j+0] * sc); x.y = tf32c(v[4*j+1] * sc);
        x.z = tf32c(v[4*j+2] * sc); x.w = tf32c(v[4*j+3] * sc);
        ((uint4*)dst)[j] = x;
    }
}

__global__ __launch_bounds__(128, 6)
void pconv_mma(const float* __restrict__ in_pc,
               const int*   __restrict__ nid_g,
               const float* __restrict__ wts,
               const float* __restrict__ bias,
               const float* __restrict__ pnb,
               const float* __restrict__ wres,
               float* __restrict__ out)
{
    // layout: A0 @0, A1 @TILEF, W0 @2*TILEF, W1 @3*TILEF
    __shared__ float sm[4 * TILEF + 32];
    float* pm_s  = sm + 4 * TILEF;
    int*   nid_s = (int*)(sm + 4 * TILEF + 16);

    const int tid  = threadIdx.x;
    const int lane = tid & 31;
    const int wid  = tid >> 5;
    const int p    = blockIdx.x;

    const int bg  = (wid >> 1) * 32;
    const int og  = (wid & 1) * 32;
    const int g   = lane >> 2;
    const int tig = lane & 3;

    const int srow = tid >> 1;
    const int scol = (tid & 1) * 16;

    if (tid < MNB) {
        int nv = nid_g[p * MNB + tid];
        nid_s[tid] = nv;
        pm_s[tid] = (nv != IN_PN) ? fabsf(pnb[p * MNB + tid]) : 0.0f;
    }
    __syncthreads();
    if (tid == 0) {
        float s = 1e-8f;
        #pragma unroll
        for (int m = 0; m < MNB; m++) s += pm_s[m];
        float inv = 1.0f / s;
        #pragma unroll
        for (int m = 0; m < MNB; m++) pm_s[m] *= inv;
    }
    __syncthreads();

    const float* wp    = wts + (size_t)p * (MNB * CIN * COUT);
    const float* inrow = in_pc + (size_t)srow * (IN_PN * CIN) + scol;
    const u32 smb = (u32)__cvta_generic_to_shared(sm);

    // ldmatrix lane addresses (within A0 / W0 tiles) — verified mapping
    const u32 aFrag = smb + (u32)(bg + (lane & 15)) * (SLOT * 4u) + (u32)(lane >> 4) * 16u;
    const u32 wFrag = smb + (u32)(2 * TB) + (u32)(og + lane) * (SLOT * 4u);
    const u32 aHalf = 16u * SLOT * 4u;
    const u32 stOff = (u32)(srow * SLOT + scol) * 4u;

    float rs[16];
    #pragma unroll
    for (int i = 0; i < 16; i++) rs[i] = 0.0f;

    // ---- prologue: stage slice 0 (W + gathered In, all cp.async) ----
    {
        const float* wsrc = wp + (size_t)srow * CIN + scol;
        u32 wdst = smb + 2u * TB + stOff;
        #pragma unroll
        for (int j = 0; j < 4; j++) cpasync16(wdst + 16u * j, wsrc + 4 * j);

        int nv = nid_s[0];
        const float* isrc = inrow + (size_t)((nv == IN_PN) ? 0 : nv) * CIN;
        u32 sb = (nv == IN_PN) ? 0u : 16u;
        u32 adst = smb + stOff;
        #pragma unroll
        for (int j = 0; j < 4; j++) cpasync16z(adst + 16u * j, isrc + 4 * j, sb);
        cpcommit();
        cpwait0();
    }
    __syncthreads();

    float acc[2][4][4];
    #pragma unroll
    for (int b = 0; b < 2; b++)
        #pragma unroll
        for (int j = 0; j < 4; j++)
            #pragma unroll
            for (int e = 0; e < 4; e++) acc[b][j][e] = 0.0f;

    #pragma unroll 1
    for (int m = 0; m < MNB; m++) {
        const u32 cOff = (m & 1) ? (u32)TB : 0u;   // current tile byte offset
        const u32 nOff = (u32)TB - cOff;           // next tile byte offset

        if (m < MNB - 1) {
            const float* wsrc = wp + (size_t)(m + 1) * (CIN * COUT)
                              + (size_t)srow * CIN + scol;
            u32 wdst = smb + 2u * TB + nOff + stOff;
            #pragma unroll
            for (int j = 0; j < 4; j++) cpasync16(wdst + 16u * j, wsrc + 4 * j);

            int nv = nid_s[m + 1];
            const float* isrc = inrow + (size_t)((nv == IN_PN) ? 0 : nv) * CIN;
            u32 sb = (nv == IN_PN) ? 0u : 16u;
            u32 adst = smb + nOff + stOff;
            #pragma unroll
            for (int j = 0; j < 4; j++) cpasync16z(adst + 16u * j, isrc + 4 * j, sb);
            cpcommit();
        }

        slice_mma(aFrag + cOff, aFrag + cOff + aHalf, wFrag + cOff, acc);

        // residual pre-reduction from the CURRENT landed A tile (raw fp32)
        {
            const float* at = sm + (cOff >> 2) + srow * SLOT + scol;
            const float pmv = pm_s[m];
            #pragma unroll
            for (int j = 0; j < 4; j++) {
                float4 q = ((const float4*)at)[j];
                rs[4*j+0] = fmaf(pmv, q.x, rs[4*j+0]);
                rs[4*j+1] = fmaf(pmv, q.y, rs[4*j+1]);
                rs[4*j+2] = fmaf(pmv, q.z, rs[4*j+2]);
                rs[4*j+3] = fmaf(pmv, q.w, rs[4*j+3]);
            }
        }

        if (m < MNB - 1) {
            cpwait0();
            __syncthreads();
        }
    }

    // ---- residual slice into freed buffers A1/W1 (last slice used A0/W0) ----
    const float C = 0.70710678118654752f;   // sqrt(0.5)
    sts16(sm + TILEF + srow * SLOT + scol, rs, 1.0f);   // rna cvt: unbiased
    {
        float vw[16];
        ldg16(vw, wres + (size_t)srow * CIN + scol);
        sts16(sm + 3 * TILEF + srow * SLOT + scol, vw, C);  // sqrt(RR)*wres, rna
    }

    // acc <- C * elu(CORR2*acc + bias)
    // CORR2 = (1 + 2^-11*ln2)^2 cancels truncation bias on BOTH tf32 operands
    const float CORR2 = 1.000676f;
    const float* brow = bias + (size_t)p * COUT;
    #pragma unroll
    for (int j = 0; j < 4; j++) {
        const int o0 = og + 8 * j + 2 * tig;
        float2 bb = *(const float2*)(brow + o0);
        #pragma unroll
        for (int b = 0; b < 2; b++) {
            float x0 = fmaf(acc[b][j][0], CORR2, bb.x);
            float x1 = fmaf(acc[b][j][1], CORR2, bb.y);
            float x2 = fmaf(acc[b][j][2], CORR2, bb.x);
            float x3 = fmaf(acc[b][j][3], CORR2, bb.y);
            x0 = (x0 > 0.0f) ? x0 : expm1f(x0);
            x1 = (x1 > 0.0f) ? x1 : expm1f(x1);
            x2 = (x2 > 0.0f) ? x2 : expm1f(x2);
            x3 = (x3 > 0.0f) ? x3 : expm1f(x3);
            acc[b][j][0] = C * x0; acc[b][j][1] = C * x1;
            acc[b][j][2] = C * x2; acc[b][j][3] = C * x3;
        }
    }
    __syncthreads();

    // residual MMA accumulates in place (A1/W1 both rna tf32 — unbiased)
    slice_mma(aFrag + TB, aFrag + TB + aHalf, wFrag + TB, acc);

    // ---- store: out[b][p][o] ----
    #pragma unroll
    for (int j = 0; j < 4; j++) {
        const int o0 = og + 8 * j + 2 * tig;
        #pragma unroll
        for (int b = 0; b < 2; b++) {
            const int r0 = bg + 16 * b + g;
            float2 v0 = { acc[b][j][0], acc[b][j][1] };
            float2 v1 = { acc[b][j][2], acc[b][j][3] };
            *(float2*)(out + ((size_t)r0       * OUT_PN + p) * COUT + o0) = v0;
            *(float2*)(out + ((size_t)(r0 + 8) * OUT_PN + p) * COUT + o0) = v1;
        }
    }
}

extern "C" void kernel_launch(void* const* d_in, const int* in_sizes, int n_in,
                              void* d_out, int out_size)
{
    const float* in_pc = (const float*)d_in[0];
    const int*   nid   = (const int*)  d_in[1];
    const float* wts   = (const float*)d_in[2];
    const float* bias  = (const float*)d_in[3];
    const float* pnb   = (const float*)d_in[4];
    const float* wres  = (const float*)d_in[5];
    float* out = (float*)d_out;

    pconv_mma<<<OUT_PN, 128>>>(in_pc, nid, wts, bias, pnb, wres, out);
}